// round 2
// baseline (speedup 1.0000x reference)
#include <cuda_runtime.h>
#include <cuda_bf16.h>

// WeightedNHotEncodingLayer: out[row, ids[k]] += w[k] for k in row's CSR range.
// Output (16384 x 8192 fp32 = 512MB) dominates: write it exactly once.
//
// Kernel 1: exclusive scan of row_lengths -> row start offsets (generic, cheap).
// Kernel 2: one CTA per row. Zero 32KB smem row, smem-atomicAdd the row's
//           nonzeros, stream row to gmem with float4 __stcs (L2 bypass hint).

#define MAX_ROWS 32768
__device__ int g_row_offsets[MAX_ROWS];

__global__ void __launch_bounds__(1024)
scan_row_lengths(const int* __restrict__ lens,
                 int* __restrict__ offs, int n) {
    __shared__ int partial[1024];
    const int t = threadIdx.x;
    const int items = (n + 1023) >> 10;      // per-thread chunk (16 for n=16384)
    const int base = t * items;

    // Sum this thread's chunk with vectorized loads where aligned.
    int s = 0;
    if ((items & 3) == 0 && base + items <= n) {
        const int4* l4 = reinterpret_cast<const int4*>(lens + base);
        #pragma unroll 4
        for (int j = 0; j < items / 4; j++) {
            int4 v = __ldg(&l4[j]);
            s += v.x + v.y + v.z + v.w;
        }
    } else {
        for (int j = 0; j < items; j++) {
            int i = base + j;
            if (i < n) s += lens[i];
        }
    }
    partial[t] = s;
    __syncthreads();
    // Hillis-Steele inclusive scan over 1024 partials
    #pragma unroll
    for (int d = 1; d < 1024; d <<= 1) {
        int v = (t >= d) ? partial[t - d] : 0;
        __syncthreads();
        partial[t] += v;
        __syncthreads();
    }
    int run = partial[t] - s;  // exclusive prefix of this thread's chunk
    for (int j = 0; j < items; j++) {
        int i = base + j;
        if (i < n) {
            offs[i] = run;
            run += lens[i];
        }
    }
}

__global__ void __launch_bounds__(256)
nhot_row_kernel(const int* __restrict__ ids,
                const float* __restrict__ w,
                const int* __restrict__ lens,
                const int* __restrict__ offs,
                float* __restrict__ out,
                int nb) {
    extern __shared__ float srow[];
    const int row = blockIdx.x;
    const int t = threadIdx.x;
    const int nb4 = nb >> 2;                 // 2048 float4 slots

    // Zero the shared row (vectorized)
    float4* s4 = reinterpret_cast<float4*>(srow);
    const float4 z = make_float4(0.f, 0.f, 0.f, 0.f);
    #pragma unroll 8
    for (int i = t; i < nb4; i += 256) s4[i] = z;
    __syncthreads();

    // Scatter this row's nonzeros into smem (handles duplicate ids)
    const int len   = lens[row];
    const int start = offs[row];
    for (int j = t; j < len; j += 256) {
        int id  = __ldg(&ids[start + j]);
        float v = __ldg(&w[start + j]);
        atomicAdd(&srow[id], v);
    }
    __syncthreads();

    // Stream the row to global memory, single touch, L2-bypass hint
    float4* o4 = reinterpret_cast<float4*>(out + (size_t)row * nb);
    #pragma unroll 8
    for (int i = t; i < nb4; i += 256) __stcs(&o4[i], s4[i]);
}

extern "C" void kernel_launch(void* const* d_in, const int* in_sizes, int n_in,
                              void* d_out, int out_size) {
    const int*   ids  = (const int*)d_in[0];     // values (NNZ,1) int32
    const int*   lens = (const int*)d_in[1];     // row_lengths (B,1) int32
    const float* w    = (const float*)d_in[2];   // weight_values (NNZ,1) f32
    // d_in[3] = weight_row_lengths (identical to lens; unused)
    float* out = (float*)d_out;

    const int B  = in_sizes[1];            // 16384 rows
    const int nb = out_size / B;           // 8192 buckets

    int* offs;
    cudaGetSymbolAddress((void**)&offs, g_row_offsets);

    scan_row_lengths<<<1, 1024>>>(lens, offs, B);

    const size_t smem = (size_t)nb * sizeof(float);  // 32KB
    nhot_row_kernel<<<B, 256, smem>>>(ids, w, lens, offs, out, nb);
}